// round 1
// baseline (speedup 1.0000x reference)
#include <cuda_runtime.h>
#include <cstdint>

// Problem constants
#define B_   16
#define C_   256
#define HW_  1024
#define K_   8192
#define N_   16384            // B*H*W tokens
#define NQE  4194304          // B*C*H*W output elems for qe

// GEMM-argmin tiling
#define TM 128                 // tokens per block
#define TN 128                 // codes per tile
#define KC 16                  // C-chunk
#define KSPLIT 4
#define CPS (K_ / KSPLIT)      // codes per split = 2048

// Scratch (no allocations allowed)
__device__ unsigned long long g_best[N_];
__device__ float g_cnorm[K_];
__device__ float g_partial[B_ * C_];

// ---------------------------------------------------------------------------
// Kernel 1: codebook squared norms. One warp per code.
__global__ void cnorm_kernel(const float* __restrict__ cb) {
    int code = blockIdx.x * 8 + (threadIdx.x >> 5);
    int lane = threadIdx.x & 31;
    const float4* row = (const float4*)(cb + (size_t)code * C_);
    float s = 0.0f;
#pragma unroll
    for (int r = 0; r < 2; r++) {
        float4 v = row[lane + 32 * r];
        s += v.x * v.x + v.y * v.y + v.z * v.z + v.w * v.w;
    }
#pragma unroll
    for (int off = 16; off; off >>= 1)
        s += __shfl_xor_sync(0xFFFFFFFFu, s, off);
    if (lane == 0) g_cnorm[code] = s;
}

// ---------------------------------------------------------------------------
// Kernel 2: init per-token best to +inf
__global__ void init_kernel() {
    int i = blockIdx.x * 256 + threadIdx.x;
    if (i < N_) g_best[i] = 0xFFFFFFFFFFFFFFFFull;
}

// ---------------------------------------------------------------------------
// Monotonic map: float -> uint32 preserving order (handles negatives)
__device__ __forceinline__ unsigned int fkey(float f) {
    unsigned int b = __float_as_uint(f);
    return (b & 0x80000000u) ? ~b : (b | 0x80000000u);
}

// Kernel 3: fused distance GEMM + running argmin.
// grid = (N/TM, KSPLIT), block = 256 (16x16), 8x8 per thread.
// score = cnorm[j] - 2 * <x_n, e_j>   (x-norm constant per token, irrelevant to argmin)
__global__ void __launch_bounds__(256, 2)
argmin_kernel(const float* __restrict__ x, const float* __restrict__ cb) {
    __shared__ float xs[KC][TM + 2];   // [c-chunk][token], pad=2 keeps float2 alignment
    __shared__ float cs[KC][TN + 2];   // [c-chunk][code]

    const int tid = threadIdx.x;
    const int tx = tid & 15;
    const int ty = tid >> 4;
    const int n0 = blockIdx.x * TM;
    const int b  = n0 >> 10;           // HW_ = 1024
    const int hw0 = n0 & 1023;
    const float* xbase = x + (size_t)b * C_ * HW_ + hw0;  // xbase[c*HW_ + t]

    unsigned long long best[8];
#pragma unroll
    for (int i = 0; i < 8; i++) best[i] = 0xFFFFFFFFFFFFFFFFull;

    const int jbase = blockIdx.y * CPS;

    for (int jt = 0; jt < CPS; jt += TN) {
        const int j0 = jbase + jt;
        float acc[8][8];
#pragma unroll
        for (int i = 0; i < 8; i++)
#pragma unroll
            for (int u = 0; u < 8; u++) acc[i][u] = 0.0f;

        for (int c0 = 0; c0 < C_; c0 += KC) {
            // load x tile: 2048 elems. idx = tid + r*256; kc = idx>>7; t = idx&127
#pragma unroll
            for (int r = 0; r < 8; r++) {
                int idx = tid + r * 256;
                int kc = idx >> 7, t = idx & 127;
                xs[kc][t] = xbase[(size_t)(c0 + kc) * HW_ + t];
            }
            // load codebook tile transposed: j = idx>>4, kc = idx&15 (coalesced 64B reads)
#pragma unroll
            for (int r = 0; r < 8; r++) {
                int idx = tid + r * 256;
                int j = idx >> 4, kc = idx & 15;
                cs[kc][j] = cb[(size_t)(j0 + j) * C_ + (c0 + kc)];
            }
            __syncthreads();

#pragma unroll
            for (int kc = 0; kc < KC; kc++) {
                float a[8], bb[8];
                // float2 fragments, strided mapping: tokens 2*ty + 32*i + e, codes 2*tx + 32*u + e
#pragma unroll
                for (int i = 0; i < 4; i++) {
                    float2 v = *(const float2*)&xs[kc][2 * ty + 32 * i];
                    a[2 * i] = v.x; a[2 * i + 1] = v.y;
                }
#pragma unroll
                for (int u = 0; u < 4; u++) {
                    float2 v = *(const float2*)&cs[kc][2 * tx + 32 * u];
                    bb[2 * u] = v.x; bb[2 * u + 1] = v.y;
                }
#pragma unroll
                for (int i = 0; i < 8; i++)
#pragma unroll
                    for (int u = 0; u < 8; u++)
                        acc[i][u] += a[i] * bb[u];
            }
            __syncthreads();
        }

        // fold this tile into running best
#pragma unroll
        for (int u = 0; u < 8; u++) {
            int j = j0 + 2 * tx + 32 * (u >> 1) + (u & 1);
            float cn = g_cnorm[j];
#pragma unroll
            for (int i = 0; i < 8; i++) {
                float s = fmaf(-2.0f, acc[i][u], cn);
                unsigned long long p =
                    ((unsigned long long)fkey(s) << 32) | (unsigned int)j;
                if (p < best[i]) best[i] = p;
            }
        }
    }

    // reduce across tx (16-lane groups within warp), then atomic combine across KSPLIT
#pragma unroll
    for (int i = 0; i < 8; i++) {
        unsigned long long v = best[i];
#pragma unroll
        for (int off = 8; off; off >>= 1) {
            unsigned long long o = __shfl_xor_sync(0xFFFFFFFFu, v, off);
            if (o < v) v = o;
        }
        if (tx == 0) {
            int n = n0 + 2 * ty + 32 * (i >> 1) + (i & 1);
            atomicMin(&g_best[n], v);
        }
    }
}

// ---------------------------------------------------------------------------
// Kernel 4: gather q, write qe + indices, per-block loss partials.
// grid = B*C blocks (one (b,c) row of HW each), 256 threads, 4 elems/thread.
__global__ void gather_kernel(const float* __restrict__ x,
                              const float* __restrict__ cb,
                              float* __restrict__ out) {
    const int bc = blockIdx.x;           // b*256 + c
    const int b = bc >> 8, c = bc & 255;
    const float* xrow = x + (size_t)bc * HW_;
    float* orow = out + (size_t)bc * HW_;
    float lsum = 0.0f;
#pragma unroll
    for (int r = 0; r < 4; r++) {
        int hw = threadIdx.x + r * 256;
        int n = b * HW_ + hw;
        unsigned int idx = (unsigned int)(g_best[n] & 0xFFFFFFFFull);
        float q = cb[(size_t)idx * C_ + c];
        float d = xrow[hw] - q;
        lsum += d * d;
        orow[hw] = q;
        if (c == 0) out[NQE + 1 + n] = (float)idx;   // indices section
    }
    __shared__ float red[256];
    red[threadIdx.x] = lsum;
    __syncthreads();
#pragma unroll
    for (int s = 128; s; s >>= 1) {
        if (threadIdx.x < s) red[threadIdx.x] += red[threadIdx.x + s];
        __syncthreads();
    }
    if (threadIdx.x == 0) g_partial[bc] = red[0];
}

// ---------------------------------------------------------------------------
// Kernel 5: deterministic final loss reduction
__global__ void loss_kernel(float* __restrict__ out) {
    __shared__ float red[256];
    float s = 0.0f;
    for (int i = threadIdx.x; i < B_ * C_; i += 256) s += g_partial[i];
    red[threadIdx.x] = s;
    __syncthreads();
#pragma unroll
    for (int st = 128; st; st >>= 1) {
        if (threadIdx.x < st) red[threadIdx.x] += red[threadIdx.x + st];
        __syncthreads();
    }
    if (threadIdx.x == 0)
        out[NQE] = red[0] / (float)((size_t)N_ * C_);
}

// ---------------------------------------------------------------------------
extern "C" void kernel_launch(void* const* d_in, const int* in_sizes, int n_in,
                              void* d_out, int out_size) {
    const float* x  = (const float*)d_in[0];   // [16,256,32,32]
    const float* cb = (const float*)d_in[1];   // [8192,256]
    float* out = (float*)d_out;                // [qe | loss | indices]

    cnorm_kernel<<<K_ / 8, 256>>>(cb);
    init_kernel<<<N_ / 256, 256>>>();
    dim3 grid(N_ / TM, KSPLIT);
    argmin_kernel<<<grid, 256>>>(x, cb);
    gather_kernel<<<B_ * C_, 256>>>(x, cb, out);
    loss_kernel<<<1, 256>>>(out);
}

// round 2
// speedup vs baseline: 1.0136x; 1.0136x over previous
#include <cuda_runtime.h>
#include <cstdint>

// Problem constants
#define B_   16
#define C_   256
#define HW_  1024
#define K_   8192
#define N_   16384            // B*H*W tokens
#define NQE  4194304          // B*C*H*W output elems for qe

// GEMM-argmin tiling
#define TM 128                 // tokens per block
#define TN 128                 // codes per tile
#define KC 16                  // C-chunk
#define KSPLIT 4
#define CPS (K_ / KSPLIT)      // codes per split = 2048

// Scratch (no allocations allowed)
__device__ unsigned long long g_best[N_];
__device__ float g_cnorm[K_];
__device__ float g_partial[B_ * C_];

// ---------------------------------------------------------------------------
// Kernel 1: codebook squared norms. One warp per code.
__global__ void cnorm_kernel(const float* __restrict__ cb) {
    int code = blockIdx.x * 8 + (threadIdx.x >> 5);
    int lane = threadIdx.x & 31;
    const float4* row = (const float4*)(cb + (size_t)code * C_);
    float s = 0.0f;
#pragma unroll
    for (int r = 0; r < 2; r++) {
        float4 v = row[lane + 32 * r];
        s += v.x * v.x + v.y * v.y + v.z * v.z + v.w * v.w;
    }
#pragma unroll
    for (int off = 16; off; off >>= 1)
        s += __shfl_xor_sync(0xFFFFFFFFu, s, off);
    if (lane == 0) g_cnorm[code] = s;
}

// ---------------------------------------------------------------------------
// Kernel 2: init per-token best to +inf
__global__ void init_kernel() {
    int i = blockIdx.x * 256 + threadIdx.x;
    if (i < N_) g_best[i] = 0xFFFFFFFFFFFFFFFFull;
}

// ---------------------------------------------------------------------------
// Monotonic map: float -> uint32 preserving order (handles negatives)
__device__ __forceinline__ unsigned int fkey(float f) {
    unsigned int b = __float_as_uint(f);
    return (b & 0x80000000u) ? ~b : (b | 0x80000000u);
}

// Packed f32x2 helpers (FFMA2 path — ptxas never auto-fuses; PTX only)
__device__ __forceinline__ unsigned long long dup_f32x2(float a) {
    unsigned long long r;
    unsigned int u = __float_as_uint(a);
    asm("mov.b64 %0, {%1, %1};" : "=l"(r) : "r"(u));
    return r;
}
__device__ __forceinline__ void fma_f32x2(unsigned long long& acc,
                                          unsigned long long a,
                                          unsigned long long b) {
    asm("fma.rn.f32x2 %0, %1, %2, %0;" : "+l"(acc) : "l"(a), "l"(b));
}
__device__ __forceinline__ void unpack_f32x2(unsigned long long v,
                                             float& lo, float& hi) {
    unsigned int ulo, uhi;
    asm("mov.b64 {%0, %1}, %2;" : "=r"(ulo), "=r"(uhi) : "l"(v));
    lo = __uint_as_float(ulo);
    hi = __uint_as_float(uhi);
}

// Kernel 3: fused distance GEMM + running argmin, packed f32x2 FMA.
// grid = (N/TM, KSPLIT), block = 256 (16x16), 8 tokens x 8 codes per thread
// (codes held as 4 packed f32x2 accumulators per token row).
// score = cnorm[j] - 2 * <x_n, e_j>   (x-norm constant per token, irrelevant)
__global__ void __launch_bounds__(256, 2)
argmin_kernel(const float* __restrict__ x, const float* __restrict__ cb) {
    __shared__ float xs[KC][TM + 2];   // [c-chunk][token]; rows stay 8B-aligned
    __shared__ float cs[KC][TN + 2];   // [c-chunk][code]

    const int tid = threadIdx.x;
    const int tx = tid & 15;
    const int ty = tid >> 4;
    const int n0 = blockIdx.x * TM;
    const int b  = n0 >> 10;           // HW_ = 1024
    const int hw0 = n0 & 1023;
    const float* xbase = x + (size_t)b * C_ * HW_ + hw0;  // xbase[c*HW_ + t]

    unsigned long long best[8];
#pragma unroll
    for (int i = 0; i < 8; i++) best[i] = 0xFFFFFFFFFFFFFFFFull;

    const int jbase = blockIdx.y * CPS;

    for (int jt = 0; jt < CPS; jt += TN) {
        const int j0 = jbase + jt;
        unsigned long long acc2[8][4];   // [token i][code-pair up]
#pragma unroll
        for (int i = 0; i < 8; i++)
#pragma unroll
            for (int u = 0; u < 4; u++) acc2[i][u] = 0ull;

        for (int c0 = 0; c0 < C_; c0 += KC) {
            // load x tile: 2048 elems. idx = tid + r*256; kc = idx>>7; t = idx&127
#pragma unroll
            for (int r = 0; r < 8; r++) {
                int idx = tid + r * 256;
                int kc = idx >> 7, t = idx & 127;
                xs[kc][t] = xbase[(size_t)(c0 + kc) * HW_ + t];
            }
            // load codebook tile transposed: j = idx>>4, kc = idx&15 (64B reads)
#pragma unroll
            for (int r = 0; r < 8; r++) {
                int idx = tid + r * 256;
                int j = idx >> 4, kc = idx & 15;
                cs[kc][j] = cb[(size_t)(j0 + j) * C_ + (c0 + kc)];
            }
            __syncthreads();

#pragma unroll
            for (int kc = 0; kc < KC; kc++) {
                // token fragment: pairs at 2*ty + 32*i', duplicated into f32x2
                unsigned long long a2[8];
#pragma unroll
                for (int i = 0; i < 4; i++) {
                    float2 v = *(const float2*)&xs[kc][2 * ty + 32 * i];
                    a2[2 * i]     = dup_f32x2(v.x);
                    a2[2 * i + 1] = dup_f32x2(v.y);
                }
                // code fragment: packed pairs straight from smem (8B aligned)
                unsigned long long b2[4];
#pragma unroll
                for (int u = 0; u < 4; u++)
                    b2[u] = *(const unsigned long long*)&cs[kc][2 * tx + 32 * u];
#pragma unroll
                for (int i = 0; i < 8; i++)
#pragma unroll
                    for (int u = 0; u < 4; u++)
                        fma_f32x2(acc2[i][u], a2[i], b2[u]);
            }
            __syncthreads();
        }

        // fold this tile into running best
#pragma unroll
        for (int u = 0; u < 4; u++) {
            int jlo = j0 + 2 * tx + 32 * u;
            float cn_lo = g_cnorm[jlo];
            float cn_hi = g_cnorm[jlo + 1];
#pragma unroll
            for (int i = 0; i < 8; i++) {
                float dlo, dhi;
                unpack_f32x2(acc2[i][u], dlo, dhi);
                float slo = fmaf(-2.0f, dlo, cn_lo);
                float shi = fmaf(-2.0f, dhi, cn_hi);
                unsigned long long plo =
                    ((unsigned long long)fkey(slo) << 32) | (unsigned int)jlo;
                unsigned long long phi =
                    ((unsigned long long)fkey(shi) << 32) | (unsigned int)(jlo + 1);
                if (phi < plo) plo = phi;
                if (plo < best[i]) best[i] = plo;
            }
        }
    }

    // reduce across tx (16-lane groups within warp), then atomic across KSPLIT
#pragma unroll
    for (int i = 0; i < 8; i++) {
        unsigned long long v = best[i];
#pragma unroll
        for (int off = 8; off; off >>= 1) {
            unsigned long long o = __shfl_xor_sync(0xFFFFFFFFu, v, off);
            if (o < v) v = o;
        }
        if (tx == 0) {
            int n = n0 + 2 * ty + 32 * (i >> 1) + (i & 1);
            atomicMin(&g_best[n], v);
        }
    }
}

// ---------------------------------------------------------------------------
// Kernel 4: gather q, write qe + indices, per-block loss partials.
// grid = B*C blocks (one (b,c) row of HW each), 256 threads, 4 elems/thread.
__global__ void gather_kernel(const float* __restrict__ x,
                              const float* __restrict__ cb,
                              float* __restrict__ out) {
    const int bc = blockIdx.x;           // b*256 + c
    const int b = bc >> 8, c = bc & 255;
    const float* xrow = x + (size_t)bc * HW_;
    float* orow = out + (size_t)bc * HW_;
    float lsum = 0.0f;
#pragma unroll
    for (int r = 0; r < 4; r++) {
        int hw = threadIdx.x + r * 256;
        int n = b * HW_ + hw;
        unsigned int idx = (unsigned int)(g_best[n] & 0xFFFFFFFFull);
        float q = cb[(size_t)idx * C_ + c];
        float d = xrow[hw] - q;
        lsum += d * d;
        orow[hw] = q;
        if (c == 0) out[NQE + 1 + n] = (float)idx;   // indices section
    }
    __shared__ float red[256];
    red[threadIdx.x] = lsum;
    __syncthreads();
#pragma unroll
    for (int s = 128; s; s >>= 1) {
        if (threadIdx.x < s) red[threadIdx.x] += red[threadIdx.x + s];
        __syncthreads();
    }
    if (threadIdx.x == 0) g_partial[bc] = red[0];
}

// ---------------------------------------------------------------------------
// Kernel 5: deterministic final loss reduction
__global__ void loss_kernel(float* __restrict__ out) {
    __shared__ float red[256];
    float s = 0.0f;
    for (int i = threadIdx.x; i < B_ * C_; i += 256) s += g_partial[i];
    red[threadIdx.x] = s;
    __syncthreads();
#pragma unroll
    for (int st = 128; st; st >>= 1) {
        if (threadIdx.x < st) red[threadIdx.x] += red[threadIdx.x + st];
        __syncthreads();
    }
    if (threadIdx.x == 0)
        out[NQE] = red[0] / (float)((size_t)N_ * C_);
}

// ---------------------------------------------------------------------------
extern "C" void kernel_launch(void* const* d_in, const int* in_sizes, int n_in,
                              void* d_out, int out_size) {
    const float* x  = (const float*)d_in[0];   // [16,256,32,32]
    const float* cb = (const float*)d_in[1];   // [8192,256]
    float* out = (float*)d_out;                // [qe | loss | indices]

    cnorm_kernel<<<K_ / 8, 256>>>(cb);
    init_kernel<<<N_ / 256, 256>>>();
    dim3 grid(N_ / TM, KSPLIT);
    argmin_kernel<<<grid, 256>>>(x, cb);
    gather_kernel<<<B_ * C_, 256>>>(x, cb, out);
    loss_kernel<<<1, 256>>>(out);
}

// round 5
// speedup vs baseline: 1.3515x; 1.3334x over previous
#include <cuda_runtime.h>
#include <cstdint>

// Problem constants
#define B_   16
#define C_   256
#define HW_  1024
#define K_   8192
#define N_   16384            // tokens
#define NQE  4194304          // qe elems

// Tiling
#define TM 128                 // tokens per CTA
#define TN 128                 // codes per CTA
#define KCH 32                 // K chunk (floats)
#define NCHUNK (C_ / KCH)      // 8
#define NCAND 256              // candidates per token (64 ctaY * 2 nwarps * 2)
#define MARGIN 0.05f

// smem layout (in floats, per stage)
#define A_STRIDE 136
#define B_STRIDE 36
#define OFF_AH 0
#define OFF_AL (32 * A_STRIDE)
#define OFF_BH (2 * 32 * A_STRIDE)
#define OFF_BL (2 * 32 * A_STRIDE + 128 * B_STRIDE)
#define STAGE_F (2 * 32 * A_STRIDE + 2 * 128 * B_STRIDE)
#define SMEM_BYTES (2 * STAGE_F * 4)

// Scratch
__device__ unsigned long long g_cand[(size_t)N_ * NCAND];   // 32MB
__device__ unsigned int g_idx[N_];
__device__ float g_cnorm[K_];
__device__ float g_partial[B_ * C_];

__device__ __forceinline__ unsigned int fkey(float f) {
    unsigned int b = __float_as_uint(f);
    return (b & 0x80000000u) ? ~b : (b | 0x80000000u);
}
__device__ __forceinline__ float unfkey(unsigned int k) {
    unsigned int b = (k & 0x80000000u) ? (k & 0x7FFFFFFFu) : ~k;
    return __uint_as_float(b);
}
__device__ __forceinline__ uint32_t f2tf32(float v) {
    uint32_t r;
    asm("cvt.rna.tf32.f32 %0, %1;" : "=r"(r) : "f"(v));
    return r;
}

#define MMA_TF32(D, A, B0, B1)                                             \
    asm volatile("mma.sync.aligned.m16n8k8.row.col.f32.tf32.tf32.f32 "     \
        "{%0,%1,%2,%3},{%4,%5,%6,%7},{%8,%9},{%0,%1,%2,%3};"               \
        : "+f"((D)[0]), "+f"((D)[1]), "+f"((D)[2]), "+f"((D)[3])           \
        : "r"((A)[0]), "r"((A)[1]), "r"((A)[2]), "r"((A)[3]),              \
          "r"(B0), "r"(B1))

// ---------------------------------------------------------------------------
// Kernel 1: codebook squared norms
__global__ void cnorm_kernel(const float* __restrict__ cb) {
    int code = blockIdx.x * 8 + (threadIdx.x >> 5);
    int lane = threadIdx.x & 31;
    const float4* row = (const float4*)(cb + (size_t)code * C_);
    float s = 0.0f;
#pragma unroll
    for (int r = 0; r < 2; r++) {
        float4 v = row[lane + 32 * r];
        s += v.x * v.x + v.y * v.y + v.z * v.z + v.w * v.w;
    }
#pragma unroll
    for (int off = 16; off; off >>= 1)
        s += __shfl_xor_sync(0xFFFFFFFFu, s, off);
    if (lane == 0) g_cnorm[code] = s;
}

// ---------------------------------------------------------------------------
// Kernel 2: mma.sync tf32 (3x split) distance GEMM, top-2 candidates per
// n-warp per token, race-free writes. grid=(128,64), block=256 (4m x 2n warps).
__global__ void __launch_bounds__(256, 1)
argmin_mma_kernel(const float* __restrict__ x, const float* __restrict__ cb) {
    extern __shared__ float smemf[];
    __shared__ float cnS[TN];

    const int tid = threadIdx.x;
    const int wid = tid >> 5;
    const int lane = tid & 31;
    const int g  = lane >> 2;
    const int tg = lane & 3;
    const int m0w = (wid & 3) * 32;
    const int n0w = (wid >> 2) * 64;

    const int n0tok = blockIdx.x * TM;
    const int b   = n0tok >> 10;
    const int hw0 = n0tok & 1023;
    const int j0  = blockIdx.y * TN;

    if (tid < TN) cnS[tid] = g_cnorm[j0 + tid];

    const float* ga = x + (size_t)b * C_ * HW_ + hw0;
    const float* gb = cb + (size_t)j0 * C_;

    float d[2][8][4];
#pragma unroll
    for (int i = 0; i < 2; i++)
#pragma unroll
        for (int j = 0; j < 8; j++)
#pragma unroll
            for (int e = 0; e < 4; e++) d[i][j][e] = 0.0f;

    float  va[16];
    float4 vb[4];

    auto gld = [&](int k) {
        const int c0 = k * KCH;
#pragma unroll
        for (int r = 0; r < 16; r++) {
            int idx = tid + r * 256;
            va[r] = ga[(size_t)(c0 + (idx >> 7)) * HW_ + (idx & 127)];
        }
#pragma unroll
        for (int s = 0; s < 4; s++) {
            int f4 = tid + s * 256;
            int rowB = f4 >> 3, ch = f4 & 7;
            vb[s] = *(const float4*)(gb + (size_t)rowB * C_ + c0 + ch * 4);
        }
    };

    auto sts = [&](int stg) {
        float* base = smemf + stg * STAGE_F;
        float* aH = base + OFF_AH;
        float* aL = base + OFF_AL;
        float* bH = base + OFF_BH;
        float* bL = base + OFF_BL;
#pragma unroll
        for (int r = 0; r < 16; r++) {
            int idx = tid + r * 256;
            int c = idx >> 7, t = idx & 127;
            float v = va[r];
            uint32_t hb = f2tf32(v);
            float hf = __uint_as_float(hb);
            uint32_t lb = f2tf32(v - hf);
            aH[c * A_STRIDE + t] = hf;
            aL[c * A_STRIDE + t] = __uint_as_float(lb);
        }
#pragma unroll
        for (int s = 0; s < 4; s++) {
            int f4 = tid + s * 256;
            int rowB = f4 >> 3, ch = f4 & 7;
            float vv[4] = {vb[s].x, vb[s].y, vb[s].z, vb[s].w};
            float hi[4], lo[4];
#pragma unroll
            for (int e = 0; e < 4; e++) {
                uint32_t hb = f2tf32(vv[e]);
                hi[e] = __uint_as_float(hb);
                lo[e] = __uint_as_float(f2tf32(vv[e] - hi[e]));
            }
            *(float4*)&bH[rowB * B_STRIDE + ch * 4] = make_float4(hi[0], hi[1], hi[2], hi[3]);
            *(float4*)&bL[rowB * B_STRIDE + ch * 4] = make_float4(lo[0], lo[1], lo[2], lo[3]);
        }
    };

    auto mma_stage = [&](int stg) {
        const float* base = smemf + stg * STAGE_F;
        const uint32_t* aH = (const uint32_t*)(base + OFF_AH);
        const uint32_t* aL = (const uint32_t*)(base + OFF_AL);
        const uint32_t* bH = (const uint32_t*)(base + OFF_BH);
        const uint32_t* bL = (const uint32_t*)(base + OFF_BL);
#pragma unroll
        for (int kk = 0; kk < 4; kk++) {
            const int kr = kk * 8;
            uint32_t ah[2][4], al[2][4];
#pragma unroll
            for (int dm = 0; dm < 2; dm++) {
                int mc = m0w + 16 * dm + g;
                ah[dm][0] = aH[(kr + tg) * A_STRIDE + mc];
                ah[dm][1] = aH[(kr + tg) * A_STRIDE + mc + 8];
                ah[dm][2] = aH[(kr + tg + 4) * A_STRIDE + mc];
                ah[dm][3] = aH[(kr + tg + 4) * A_STRIDE + mc + 8];
                al[dm][0] = aL[(kr + tg) * A_STRIDE + mc];
                al[dm][1] = aL[(kr + tg) * A_STRIDE + mc + 8];
                al[dm][2] = aL[(kr + tg + 4) * A_STRIDE + mc];
                al[dm][3] = aL[(kr + tg + 4) * A_STRIDE + mc + 8];
            }
#pragma unroll
            for (int dn = 0; dn < 8; dn++) {
                int nr = n0w + 8 * dn + g;
                uint32_t bh0 = bH[nr * B_STRIDE + kr + tg];
                uint32_t bh1 = bH[nr * B_STRIDE + kr + tg + 4];
                uint32_t bl0 = bL[nr * B_STRIDE + kr + tg];
                uint32_t bl1 = bL[nr * B_STRIDE + kr + tg + 4];
#pragma unroll
                for (int dm = 0; dm < 2; dm++) {
                    MMA_TF32(d[dm][dn], ah[dm], bh0, bh1);
                    MMA_TF32(d[dm][dn], ah[dm], bl0, bl1);
                    MMA_TF32(d[dm][dn], al[dm], bh0, bh1);
                }
            }
        }
    };

    gld(0);
    sts(0);
    __syncthreads();
#pragma unroll 1
    for (int k = 0; k < NCHUNK; k++) {
        if (k + 1 < NCHUNK) gld(k + 1);
        mma_stage(k & 1);
        if (k + 1 < NCHUNK) sts((k + 1) & 1);
        __syncthreads();
    }

    // epilogue: per n-warp top-2 per token row, race-free candidate writes
#pragma unroll
    for (int dm = 0; dm < 2; dm++) {
#pragma unroll
        for (int h = 0; h < 2; h++) {
            unsigned long long p1 = 0xFFFFFFFFFFFFFFFFull;
            unsigned long long p2 = 0xFFFFFFFFFFFFFFFFull;
#pragma unroll
            for (int dn = 0; dn < 8; dn++) {
#pragma unroll
                for (int e = 0; e < 2; e++) {
                    int col = n0w + 8 * dn + 2 * tg + e;
                    float sc = fmaf(-2.0f, d[dm][dn][2 * h + e], cnS[col]);
                    unsigned long long p =
                        ((unsigned long long)fkey(sc) << 32) |
                        (unsigned int)(j0 + col);
                    if (p < p1) { p2 = p1; p1 = p; }
                    else if (p < p2) { p2 = p; }
                }
            }
            // merge sorted pairs across the 4 tg lanes
#pragma unroll
            for (int off = 1; off <= 2; off <<= 1) {
                unsigned long long q1 = __shfl_xor_sync(0xFFFFFFFFu, p1, off);
                unsigned long long q2 = __shfl_xor_sync(0xFFFFFFFFu, p2, off);
                if (q1 < p1) { p2 = (p1 < q2) ? p1 : q2; p1 = q1; }
                else         { p2 = (p2 < q1) ? p2 : q1; }
            }
            if (tg == 0) {
                int tok = n0tok + m0w + 16 * dm + 8 * h + g;
                size_t base = (size_t)tok * NCAND + blockIdx.y * 4 + (wid >> 2) * 2;
                g_cand[base] = p1;
                g_cand[base + 1] = p2;
            }
        }
    }
}

// ---------------------------------------------------------------------------
// Kernel 3: exact fp32 rerank. One warp per token over 256 candidates.
__global__ void __launch_bounds__(256)
rerank_kernel(const float* __restrict__ x, const float* __restrict__ cb) {
    const int wid = threadIdx.x >> 5;
    const int lane = threadIdx.x & 31;
    const int tok = blockIdx.x * 8 + wid;
    const unsigned long long* cand = g_cand + (size_t)tok * NCAND;

    unsigned long long v[8];
    unsigned long long mn = 0xFFFFFFFFFFFFFFFFull;
#pragma unroll
    for (int r = 0; r < 8; r++) {
        v[r] = cand[lane + 32 * r];
        if (v[r] < mn) mn = v[r];
    }
#pragma unroll
    for (int off = 16; off; off >>= 1) {
        unsigned long long o = __shfl_xor_sync(0xFFFFFFFFu, mn, off);
        if (o < mn) mn = o;
    }
    const float thr = unfkey((unsigned int)(mn >> 32)) + MARGIN;

    const int b = tok >> 10, hw = tok & 1023;
    const float* xt = x + (size_t)b * C_ * HW_ + hw;
    float xr[8];
#pragma unroll
    for (int q = 0; q < 8; q++)
        xr[q] = xt[(size_t)(lane + 32 * q) * HW_];

    float best_s = __uint_as_float(0x7F800000u);   // +inf
    unsigned int best_j = 0xFFFFFFFFu;
#pragma unroll 1
    for (int r = 0; r < 8; r++) {
        float sf = unfkey((unsigned int)(v[r] >> 32));
        unsigned int m = __ballot_sync(0xFFFFFFFFu, sf <= thr);
        while (m) {
            int src = __ffs(m) - 1;
            m &= m - 1;
            unsigned long long c = __shfl_sync(0xFFFFFFFFu, v[r], src);
            unsigned int j = (unsigned int)c;
            const float* row = cb + (size_t)j * C_;
            float dot = 0.0f;
#pragma unroll
            for (int q = 0; q < 8; q++)
                dot = fmaf(xr[q], row[lane + 32 * q], dot);
#pragma unroll
            for (int off = 16; off; off >>= 1)
                dot += __shfl_xor_sync(0xFFFFFFFFu, dot, off);
            float sc = fmaf(-2.0f, dot, g_cnorm[j]);
            if (sc < best_s || (sc == best_s && j < best_j)) {
                best_s = sc;
                best_j = j;
            }
        }
    }
    if (lane == 0) g_idx[tok] = best_j;
}

// ---------------------------------------------------------------------------
// Kernel 4: gather q, write qe + indices, per-block loss partials
__global__ void gather_kernel(const float* __restrict__ x,
                              const float* __restrict__ cb,
                              float* __restrict__ out) {
    const int bc = blockIdx.x;
    const int b = bc >> 8, c = bc & 255;
    const float* xrow = x + (size_t)bc * HW_;
    float* orow = out + (size_t)bc * HW_;
    float lsum = 0.0f;
#pragma unroll
    for (int r = 0; r < 4; r++) {
        int hw = threadIdx.x + r * 256;
        int n = b * HW_ + hw;
        unsigned int idx = g_idx[n];
        float q = cb[(size_t)idx * C_ + c];
        float dd = xrow[hw] - q;
        lsum += dd * dd;
        orow[hw] = q;
        if (c == 0) out[NQE + 1 + n] = (float)idx;
    }
    __shared__ float red[256];
    red[threadIdx.x] = lsum;
    __syncthreads();
#pragma unroll
    for (int s = 128; s; s >>= 1) {
        if (threadIdx.x < s) red[threadIdx.x] += red[threadIdx.x + s];
        __syncthreads();
    }
    if (threadIdx.x == 0) g_partial[bc] = red[0];
}

// Kernel 5: deterministic final loss reduction
__global__ void loss_kernel(float* __restrict__ out) {
    __shared__ float red[256];
    float s = 0.0f;
    for (int i = threadIdx.x; i < B_ * C_; i += 256) s += g_partial[i];
    red[threadIdx.x] = s;
    __syncthreads();
#pragma unroll
    for (int st = 128; st; st >>= 1) {
        if (threadIdx.x < st) red[threadIdx.x] += red[threadIdx.x + st];
        __syncthreads();
    }
    if (threadIdx.x == 0)
        out[NQE] = red[0] / (float)((size_t)N_ * C_);
}

// ---------------------------------------------------------------------------
extern "C" void kernel_launch(void* const* d_in, const int* in_sizes, int n_in,
                              void* d_out, int out_size) {
    const float* x  = (const float*)d_in[0];   // [16,256,32,32]
    const float* cb = (const float*)d_in[1];   // [8192,256]
    float* out = (float*)d_out;                // [qe | loss | indices]

    cudaFuncSetAttribute(argmin_mma_kernel,
                         cudaFuncAttributeMaxDynamicSharedMemorySize,
                         SMEM_BYTES);

    cnorm_kernel<<<K_ / 8, 256>>>(cb);
    dim3 grid(N_ / TM, K_ / TN);
    argmin_mma_kernel<<<grid, 256, SMEM_BYTES>>>(x, cb);
    rerank_kernel<<<N_ / 8, 256>>>(x, cb);
    gather_kernel<<<B_ * C_, 256>>>(x, cb, out);
    loss_kernel<<<1, 256>>>(out);
}

// round 6
// speedup vs baseline: 1.8000x; 1.3318x over previous
#include <cuda_runtime.h>
#include <cuda_bf16.h>
#include <cstdint>

// Problem constants
#define B_   16
#define C_   256
#define HW_  1024
#define K_   8192
#define N_   16384            // tokens
#define NQE  4194304          // qe elems

// Tiling
#define TM 128                 // tokens per CTA
#define TN 128                 // codes per CTA
#define KCH 32                 // K chunk (floats)
#define NCHUNK (C_ / KCH)      // 8
#define NCAND 256              // candidates per token (64 ctaY * 2 nwarps * 2)
#define MARGIN 0.05f

// smem: hi/lo-interleaved bf16x2 pairs, [row][kp] uint2, padded stride
#define AST 18                 // uint2 per row (16 kp + 2 pad)
#define MAT_U2 (128 * AST)     // 2304 uint2 per matrix
#define STAGE_U2 (2 * MAT_U2)  // A then B
#define SMEM_BYTES (2 * STAGE_U2 * 8)   // 73728 bytes

// Scratch
__device__ unsigned long long g_cand[(size_t)N_ * NCAND];   // 32MB
__device__ unsigned int g_idx[N_];
__device__ float g_cnorm[K_];
__device__ float g_partial[B_ * C_];

__device__ __forceinline__ unsigned int fkey(float f) {
    unsigned int b = __float_as_uint(f);
    return (b & 0x80000000u) ? ~b : (b | 0x80000000u);
}
__device__ __forceinline__ float unfkey(unsigned int k) {
    unsigned int b = (k & 0x80000000u) ? (k & 0x7FFFFFFFu) : ~k;
    return __uint_as_float(b);
}

// split (v0,v1) -> packed bf16x2 hi pair + lo pair
__device__ __forceinline__ uint2 split_pair(float v0, float v1) {
    __nv_bfloat16 h0 = __float2bfloat16_rn(v0);
    __nv_bfloat16 h1 = __float2bfloat16_rn(v1);
    float l0 = v0 - __bfloat162float(h0);
    float l1 = v1 - __bfloat162float(h1);
    __nv_bfloat162 hp; hp.x = h0; hp.y = h1;
    __nv_bfloat162 lp = __floats2bfloat162_rn(l0, l1);
    uint2 r;
    r.x = *(uint32_t*)&hp;
    r.y = *(uint32_t*)&lp;
    return r;
}

#define MMA_BF16(D, A, B0, B1)                                              \
    asm volatile("mma.sync.aligned.m16n8k16.row.col.f32.bf16.bf16.f32 "     \
        "{%0,%1,%2,%3},{%4,%5,%6,%7},{%8,%9},{%0,%1,%2,%3};"                \
        : "+f"((D)[0]), "+f"((D)[1]), "+f"((D)[2]), "+f"((D)[3])            \
        : "r"((A)[0]), "r"((A)[1]), "r"((A)[2]), "r"((A)[3]),               \
          "r"(B0), "r"(B1))

// ---------------------------------------------------------------------------
// Kernel 1: codebook squared norms
__global__ void cnorm_kernel(const float* __restrict__ cb) {
    int code = blockIdx.x * 8 + (threadIdx.x >> 5);
    int lane = threadIdx.x & 31;
    const float4* row = (const float4*)(cb + (size_t)code * C_);
    float s = 0.0f;
#pragma unroll
    for (int r = 0; r < 2; r++) {
        float4 v = row[lane + 32 * r];
        s += v.x * v.x + v.y * v.y + v.z * v.z + v.w * v.w;
    }
#pragma unroll
    for (int off = 16; off; off >>= 1)
        s += __shfl_xor_sync(0xFFFFFFFFu, s, off);
    if (lane == 0) g_cnorm[code] = s;
}

// ---------------------------------------------------------------------------
// Kernel 2: bf16 (3-term split) screening GEMM, top-2 candidates per
// n-warp per token, race-free writes. grid=(128,64), block=256 (4m x 2n warps).
__global__ void __launch_bounds__(256, 2)
argmin_mma_kernel(const float* __restrict__ x, const float* __restrict__ cb) {
    extern __shared__ uint2 smem2[];
    __shared__ float cnS[TN];

    const int tid = threadIdx.x;
    const int wid = tid >> 5;
    const int lane = tid & 31;
    const int g  = lane >> 2;
    const int tg = lane & 3;
    const int m0w = (wid & 3) * 32;
    const int n0w = (wid >> 2) * 64;

    const int n0tok = blockIdx.x * TM;
    const int b   = n0tok >> 10;
    const int hw0 = n0tok & 1023;
    const int j0  = blockIdx.y * TN;

    if (tid < TN) cnS[tid] = g_cnorm[j0 + tid];

    const float* ga = x + (size_t)b * C_ * HW_ + hw0;   // [c][t] stride HW_
    const float* gb = cb + (size_t)j0 * C_;             // [n][c] row-major

    float d[2][8][4];
#pragma unroll
    for (int i = 0; i < 2; i++)
#pragma unroll
        for (int j = 0; j < 8; j++)
#pragma unroll
            for (int e = 0; e < 4; e++) d[i][j][e] = 0.0f;

    float2 va2[8];
    float4 vb[4];

    auto gld = [&](int k) {
        const int c0 = k * KCH;
#pragma unroll
        for (int r = 0; r < 8; r++) {
            int idx = tid + r * 256;
            int t = idx & 127, kp = idx >> 7;
            va2[r].x = ga[(size_t)(c0 + 2 * kp) * HW_ + t];
            va2[r].y = ga[(size_t)(c0 + 2 * kp + 1) * HW_ + t];
        }
#pragma unroll
        for (int s = 0; s < 4; s++) {
            int f4 = tid + s * 256;
            int rowB = f4 >> 3, q = f4 & 7;
            vb[s] = *(const float4*)(gb + (size_t)rowB * C_ + c0 + q * 4);
        }
    };

    auto sts = [&](int stg) {
        uint2* As = smem2 + stg * STAGE_U2;
        uint2* Bs = As + MAT_U2;
#pragma unroll
        for (int r = 0; r < 8; r++) {
            int idx = tid + r * 256;
            int t = idx & 127, kp = idx >> 7;
            As[t * AST + kp] = split_pair(va2[r].x, va2[r].y);
        }
#pragma unroll
        for (int s = 0; s < 4; s++) {
            int f4 = tid + s * 256;
            int rowB = f4 >> 3, q = f4 & 7;
            Bs[rowB * AST + 2 * q]     = split_pair(vb[s].x, vb[s].y);
            Bs[rowB * AST + 2 * q + 1] = split_pair(vb[s].z, vb[s].w);
        }
    };

    auto mma_stage = [&](int stg) {
        const uint2* As = smem2 + stg * STAGE_U2;
        const uint2* Bs = As + MAT_U2;
#pragma unroll
        for (int kk = 0; kk < 2; kk++) {
            const int kb = kk * 8 + tg;
            uint32_t ah[2][4], al[2][4];
#pragma unroll
            for (int dm = 0; dm < 2; dm++) {
                int mc = m0w + 16 * dm + g;
                uint2 p0 = As[mc * AST + kb];
                uint2 p1 = As[(mc + 8) * AST + kb];
                uint2 p2 = As[mc * AST + kb + 4];
                uint2 p3 = As[(mc + 8) * AST + kb + 4];
                ah[dm][0] = p0.x; ah[dm][1] = p1.x; ah[dm][2] = p2.x; ah[dm][3] = p3.x;
                al[dm][0] = p0.y; al[dm][1] = p1.y; al[dm][2] = p2.y; al[dm][3] = p3.y;
            }
#pragma unroll
            for (int dn = 0; dn < 8; dn++) {
                int nr = n0w + 8 * dn + g;
                uint2 q0 = Bs[nr * AST + kb];
                uint2 q1 = Bs[nr * AST + kb + 4];
#pragma unroll
                for (int dm = 0; dm < 2; dm++) {
                    MMA_BF16(d[dm][dn], ah[dm], q0.x, q1.x);   // hi*hi
                    MMA_BF16(d[dm][dn], ah[dm], q0.y, q1.y);   // hi*lo
                    MMA_BF16(d[dm][dn], al[dm], q0.x, q1.x);   // lo*hi
                }
            }
        }
    };

    gld(0);
    sts(0);
    __syncthreads();
#pragma unroll 1
    for (int k = 0; k < NCHUNK; k++) {
        if (k + 1 < NCHUNK) gld(k + 1);
        mma_stage(k & 1);
        if (k + 1 < NCHUNK) sts((k + 1) & 1);
        __syncthreads();
    }

    // epilogue: per n-warp top-2 per token row, race-free candidate writes
#pragma unroll
    for (int dm = 0; dm < 2; dm++) {
#pragma unroll
        for (int h = 0; h < 2; h++) {
            unsigned long long p1 = 0xFFFFFFFFFFFFFFFFull;
            unsigned long long p2 = 0xFFFFFFFFFFFFFFFFull;
#pragma unroll
            for (int dn = 0; dn < 8; dn++) {
#pragma unroll
                for (int e = 0; e < 2; e++) {
                    int col = n0w + 8 * dn + 2 * tg + e;
                    float sc = fmaf(-2.0f, d[dm][dn][2 * h + e], cnS[col]);
                    unsigned long long p =
                        ((unsigned long long)fkey(sc) << 32) |
                        (unsigned int)(j0 + col);
                    if (p < p1) { p2 = p1; p1 = p; }
                    else if (p < p2) { p2 = p; }
                }
            }
#pragma unroll
            for (int off = 1; off <= 2; off <<= 1) {
                unsigned long long q1 = __shfl_xor_sync(0xFFFFFFFFu, p1, off);
                unsigned long long q2 = __shfl_xor_sync(0xFFFFFFFFu, p2, off);
                if (q1 < p1) { p2 = (p1 < q2) ? p1 : q2; p1 = q1; }
                else         { p2 = (p2 < q1) ? p2 : q1; }
            }
            if (tg == 0) {
                int tok = n0tok + m0w + 16 * dm + 8 * h + g;
                size_t base = (size_t)tok * NCAND + blockIdx.y * 4 + (wid >> 2) * 2;
                g_cand[base] = p1;
                g_cand[base + 1] = p2;
            }
        }
    }
}

// ---------------------------------------------------------------------------
// Kernel 3: exact fp32 rerank. One warp per token over 256 candidates.
__global__ void __launch_bounds__(256)
rerank_kernel(const float* __restrict__ x, const float* __restrict__ cb) {
    const int wid = threadIdx.x >> 5;
    const int lane = threadIdx.x & 31;
    const int tok = blockIdx.x * 8 + wid;
    const unsigned long long* cand = g_cand + (size_t)tok * NCAND;

    unsigned long long v[8];
    unsigned long long mn = 0xFFFFFFFFFFFFFFFFull;
#pragma unroll
    for (int r = 0; r < 8; r++) {
        v[r] = cand[lane + 32 * r];
        if (v[r] < mn) mn = v[r];
    }
#pragma unroll
    for (int off = 16; off; off >>= 1) {
        unsigned long long o = __shfl_xor_sync(0xFFFFFFFFu, mn, off);
        if (o < mn) mn = o;
    }
    const float thr = unfkey((unsigned int)(mn >> 32)) + MARGIN;

    const int b = tok >> 10, hw = tok & 1023;
    const float* xt = x + (size_t)b * C_ * HW_ + hw;
    float xr[8];
#pragma unroll
    for (int q = 0; q < 8; q++)
        xr[q] = xt[(size_t)(lane + 32 * q) * HW_];

    float best_s = __uint_as_float(0x7F800000u);   // +inf
    unsigned int best_j = 0xFFFFFFFFu;
#pragma unroll 1
    for (int r = 0; r < 8; r++) {
        float sf = unfkey((unsigned int)(v[r] >> 32));
        unsigned int m = __ballot_sync(0xFFFFFFFFu, sf <= thr);
        while (m) {
            int src = __ffs(m) - 1;
            m &= m - 1;
            unsigned long long c = __shfl_sync(0xFFFFFFFFu, v[r], src);
            unsigned int j = (unsigned int)c;
            const float* row = cb + (size_t)j * C_;
            float dot = 0.0f;
#pragma unroll
            for (int q = 0; q < 8; q++)
                dot = fmaf(xr[q], row[lane + 32 * q], dot);
#pragma unroll
            for (int off = 16; off; off >>= 1)
                dot += __shfl_xor_sync(0xFFFFFFFFu, dot, off);
            float sc = fmaf(-2.0f, dot, g_cnorm[j]);
            if (sc < best_s || (sc == best_s && j < best_j)) {
                best_s = sc;
                best_j = j;
            }
        }
    }
    if (lane == 0) g_idx[tok] = best_j;
}

// ---------------------------------------------------------------------------
// Kernel 4: gather q, write qe + indices, per-block loss partials
__global__ void gather_kernel(const float* __restrict__ x,
                              const float* __restrict__ cb,
                              float* __restrict__ out) {
    const int bc = blockIdx.x;
    const int b = bc >> 8, c = bc & 255;
    const float* xrow = x + (size_t)bc * HW_;
    float* orow = out + (size_t)bc * HW_;
    float lsum = 0.0f;
#pragma unroll
    for (int r = 0; r < 4; r++) {
        int hw = threadIdx.x + r * 256;
        int n = b * HW_ + hw;
        unsigned int idx = g_idx[n];
        float q = cb[(size_t)idx * C_ + c];
        float dd = xrow[hw] - q;
        lsum += dd * dd;
        orow[hw] = q;
        if (c == 0) out[NQE + 1 + n] = (float)idx;
    }
    __shared__ float red[256];
    red[threadIdx.x] = lsum;
    __syncthreads();
#pragma unroll
    for (int s = 128; s; s >>= 1) {
        if (threadIdx.x < s) red[threadIdx.x] += red[threadIdx.x + s];
        __syncthreads();
    }
    if (threadIdx.x == 0) g_partial[bc] = red[0];
}

// Kernel 5: deterministic final loss reduction
__global__ void loss_kernel(float* __restrict__ out) {
    __shared__ float red[256];
    float s = 0.0f;
    for (int i = threadIdx.x; i < B_ * C_; i += 256) s += g_partial[i];
    red[threadIdx.x] = s;
    __syncthreads();
#pragma unroll
    for (int st = 128; st; st >>= 1) {
        if (threadIdx.x < st) red[threadIdx.x] += red[threadIdx.x + st];
        __syncthreads();
    }
    if (threadIdx.x == 0)
        out[NQE] = red[0] / (float)((size_t)N_ * C_);
}

// ---------------------------------------------------------------------------
extern "C" void kernel_launch(void* const* d_in, const int* in_sizes, int n_in,
                              void* d_out, int out_size) {
    const float* x  = (const float*)d_in[0];   // [16,256,32,32]
    const float* cb = (const float*)d_in[1];   // [8192,256]
    float* out = (float*)d_out;                // [qe | loss | indices]

    cudaFuncSetAttribute(argmin_mma_kernel,
                         cudaFuncAttributeMaxDynamicSharedMemorySize,
                         SMEM_BYTES);

    cnorm_kernel<<<K_ / 8, 256>>>(cb);
    dim3 grid(N_ / TM, K_ / TN);
    argmin_mma_kernel<<<grid, 256, SMEM_BYTES>>>(x, cb);
    rerank_kernel<<<N_ / 8, 256>>>(x, cb);
    gather_kernel<<<B_ * C_, 256>>>(x, cb, out);
    loss_kernel<<<1, 256>>>(out);
}

// round 7
// speedup vs baseline: 2.7324x; 1.5180x over previous
#include <cuda_runtime.h>
#include <cuda_bf16.h>
#include <cstdint>

// Problem constants
#define B_   16
#define C_   256
#define HW_  1024
#define K_   8192
#define N_   16384            // tokens
#define NQE  4194304          // qe elems

// Tiling
#define TM 128                 // tokens per CTA
#define TN 128                 // codes per CTA
#define KCH 32                 // K chunk (floats) = 16 k-pairs
#define NCHUNK (C_ / KCH)      // 8
#define NCAND 256              // candidates per token (64 ctaY * 2 nwarps * 2)
#define MARGIN 0.25f

// smem (uint32 units). A: [kp][t] hi-only, stride 136 (8 mod 32 -> conflict-free)
// B: [nr][kp] uint2 (hi-pair, lo-pair), stride 18 uint2 (2-phase floor on LDS.64)
#define AST_A 136
#define A_U32 (16 * AST_A)             // 2176
#define BST 18                          // uint2 stride
#define B_U32 (128 * BST * 2)           // 4608
#define STAGE_U32 (A_U32 + B_U32)       // 6784
#define SMEM_BYTES (2 * STAGE_U32 * 4)  // 54272

// Scratch
__device__ unsigned long long g_cand[(size_t)N_ * NCAND];   // 32MB
__device__ unsigned int g_idx[N_];
__device__ float g_cnorm[K_];
__device__ float g_partial[B_ * C_];

__device__ __forceinline__ unsigned int fkey(float f) {
    unsigned int b = __float_as_uint(f);
    return (b & 0x80000000u) ? ~b : (b | 0x80000000u);
}
__device__ __forceinline__ float unfkey(unsigned int k) {
    unsigned int b = (k & 0x80000000u) ? (k & 0x7FFFFFFFu) : ~k;
    return __uint_as_float(b);
}

__device__ __forceinline__ uint32_t hi_pair(float v0, float v1) {
    __nv_bfloat162 hp = __floats2bfloat162_rn(v0, v1);
    return *(uint32_t*)&hp;
}
// (hi-pair, lo-pair) for B
__device__ __forceinline__ uint2 split_pair(float v0, float v1) {
    __nv_bfloat16 h0 = __float2bfloat16_rn(v0);
    __nv_bfloat16 h1 = __float2bfloat16_rn(v1);
    float l0 = v0 - __bfloat162float(h0);
    float l1 = v1 - __bfloat162float(h1);
    __nv_bfloat162 hp; hp.x = h0; hp.y = h1;
    __nv_bfloat162 lp = __floats2bfloat162_rn(l0, l1);
    uint2 r;
    r.x = *(uint32_t*)&hp;
    r.y = *(uint32_t*)&lp;
    return r;
}

#define MMA_BF16(D, A, B0, B1)                                              \
    asm volatile("mma.sync.aligned.m16n8k16.row.col.f32.bf16.bf16.f32 "     \
        "{%0,%1,%2,%3},{%4,%5,%6,%7},{%8,%9},{%0,%1,%2,%3};"                \
        : "+f"((D)[0]), "+f"((D)[1]), "+f"((D)[2]), "+f"((D)[3])            \
        : "r"((A)[0]), "r"((A)[1]), "r"((A)[2]), "r"((A)[3]),               \
          "r"(B0), "r"(B1))

// ---------------------------------------------------------------------------
// Kernel 1: codebook squared norms
__global__ void cnorm_kernel(const float* __restrict__ cb) {
    int code = blockIdx.x * 8 + (threadIdx.x >> 5);
    int lane = threadIdx.x & 31;
    const float4* row = (const float4*)(cb + (size_t)code * C_);
    float s = 0.0f;
#pragma unroll
    for (int r = 0; r < 2; r++) {
        float4 v = row[lane + 32 * r];
        s += v.x * v.x + v.y * v.y + v.z * v.z + v.w * v.w;
    }
#pragma unroll
    for (int off = 16; off; off >>= 1)
        s += __shfl_xor_sync(0xFFFFFFFFu, s, off);
    if (lane == 0) g_cnorm[code] = s;
}

// ---------------------------------------------------------------------------
// Kernel 2: bf16 2-term screening GEMM (hi_x * (hi_e + lo_e) = hi_x * e),
// top-2 candidates per n-warp per token. grid=(128,64), block=256 (4m x 2n).
__global__ void __launch_bounds__(256, 2)
argmin_mma_kernel(const float* __restrict__ x, const float* __restrict__ cb) {
    extern __shared__ uint32_t smemu[];
    __shared__ float cnS[TN];

    const int tid = threadIdx.x;
    const int wid = tid >> 5;
    const int lane = tid & 31;
    const int g  = lane >> 2;
    const int tg = lane & 3;
    const int m0w = (wid & 3) * 32;
    const int n0w = (wid >> 2) * 64;

    const int n0tok = blockIdx.x * TM;
    const int b   = n0tok >> 10;
    const int hw0 = n0tok & 1023;
    const int j0  = blockIdx.y * TN;

    if (tid < TN) cnS[tid] = g_cnorm[j0 + tid];

    const float* ga = x + (size_t)b * C_ * HW_ + hw0;   // [c][t] stride HW_
    const float* gb = cb + (size_t)j0 * C_;             // [n][c] row-major

    float d[2][8][4];
#pragma unroll
    for (int i = 0; i < 2; i++)
#pragma unroll
        for (int j = 0; j < 8; j++)
#pragma unroll
            for (int e = 0; e < 4; e++) d[i][j][e] = 0.0f;

    float2 va2[8];
    float4 vb[4];

    auto gld = [&](int k) {
        const int c0 = k * KCH;
#pragma unroll
        for (int r = 0; r < 8; r++) {
            int idx = tid + r * 256;
            int t = idx & 127, kp = idx >> 7;
            va2[r].x = ga[(size_t)(c0 + 2 * kp) * HW_ + t];
            va2[r].y = ga[(size_t)(c0 + 2 * kp + 1) * HW_ + t];
        }
#pragma unroll
        for (int s = 0; s < 4; s++) {
            int f4 = tid + s * 256;
            int rowB = f4 >> 3, q = f4 & 7;
            vb[s] = *(const float4*)(gb + (size_t)rowB * C_ + c0 + q * 4);
        }
    };

    auto sts = [&](int stg) {
        uint32_t* As = smemu + stg * STAGE_U32;
        uint2* Bs = (uint2*)(As + A_U32);
#pragma unroll
        for (int r = 0; r < 8; r++) {
            int idx = tid + r * 256;
            int t = idx & 127, kp = idx >> 7;
            As[kp * AST_A + t] = hi_pair(va2[r].x, va2[r].y);
        }
#pragma unroll
        for (int s = 0; s < 4; s++) {
            int f4 = tid + s * 256;
            int rowB = f4 >> 3, q = f4 & 7;
            Bs[rowB * BST + 2 * q]     = split_pair(vb[s].x, vb[s].y);
            Bs[rowB * BST + 2 * q + 1] = split_pair(vb[s].z, vb[s].w);
        }
    };

    auto mma_stage = [&](int stg) {
        const uint32_t* As = smemu + stg * STAGE_U32;
        const uint2* Bs = (const uint2*)(As + A_U32);
#pragma unroll
        for (int kk = 0; kk < 2; kk++) {
            const int kb = kk * 8 + tg;
            uint32_t ah[2][4];
#pragma unroll
            for (int dm = 0; dm < 2; dm++) {
                int mc = m0w + 16 * dm + g;
                ah[dm][0] = As[kb * AST_A + mc];
                ah[dm][1] = As[kb * AST_A + mc + 8];
                ah[dm][2] = As[(kb + 4) * AST_A + mc];
                ah[dm][3] = As[(kb + 4) * AST_A + mc + 8];
            }
#pragma unroll
            for (int dn = 0; dn < 8; dn++) {
                int nr = n0w + 8 * dn + g;
                uint2 q0 = Bs[nr * BST + kb];
                uint2 q1 = Bs[nr * BST + kb + 4];
                MMA_BF16(d[0][dn], ah[0], q0.x, q1.x);   // hi * hi
                MMA_BF16(d[1][dn], ah[1], q0.x, q1.x);
                MMA_BF16(d[0][dn], ah[0], q0.y, q1.y);   // hi * lo
                MMA_BF16(d[1][dn], ah[1], q0.y, q1.y);
            }
        }
    };

    gld(0);
    sts(0);
    __syncthreads();
#pragma unroll 1
    for (int k = 0; k < NCHUNK; k++) {
        if (k + 1 < NCHUNK) gld(k + 1);
        mma_stage(k & 1);
        if (k + 1 < NCHUNK) sts((k + 1) & 1);
        __syncthreads();
    }

    // epilogue: per n-warp top-2 per token row, race-free candidate writes
#pragma unroll
    for (int dm = 0; dm < 2; dm++) {
#pragma unroll
        for (int h = 0; h < 2; h++) {
            unsigned long long p1 = 0xFFFFFFFFFFFFFFFFull;
            unsigned long long p2 = 0xFFFFFFFFFFFFFFFFull;
#pragma unroll
            for (int dn = 0; dn < 8; dn++) {
#pragma unroll
                for (int e = 0; e < 2; e++) {
                    int col = n0w + 8 * dn + 2 * tg + e;
                    float sc = fmaf(-2.0f, d[dm][dn][2 * h + e], cnS[col]);
                    unsigned long long p =
                        ((unsigned long long)fkey(sc) << 32) |
                        (unsigned int)(j0 + col);
                    if (p < p1) { p2 = p1; p1 = p; }
                    else if (p < p2) { p2 = p; }
                }
            }
#pragma unroll
            for (int off = 1; off <= 2; off <<= 1) {
                unsigned long long q1 = __shfl_xor_sync(0xFFFFFFFFu, p1, off);
                unsigned long long q2 = __shfl_xor_sync(0xFFFFFFFFu, p2, off);
                if (q1 < p1) { p2 = (p1 < q2) ? p1 : q2; p1 = q1; }
                else         { p2 = (p2 < q1) ? p2 : q1; }
            }
            if (tg == 0) {
                int tok = n0tok + m0w + 16 * dm + 8 * h + g;
                size_t base = (size_t)tok * NCAND + blockIdx.y * 4 + (wid >> 2) * 2;
                g_cand[base] = p1;
                g_cand[base + 1] = p2;
            }
        }
    }
}

// ---------------------------------------------------------------------------
// Kernel 3: exact fp32 rerank. One warp per token over 256 candidates.
__global__ void __launch_bounds__(256)
rerank_kernel(const float* __restrict__ x, const float* __restrict__ cb) {
    const int wid = threadIdx.x >> 5;
    const int lane = threadIdx.x & 31;
    const int tok = blockIdx.x * 8 + wid;
    const unsigned long long* cand = g_cand + (size_t)tok * NCAND;

    unsigned long long v[8];
    unsigned long long mn = 0xFFFFFFFFFFFFFFFFull;
#pragma unroll
    for (int r = 0; r < 8; r++) {
        v[r] = cand[lane + 32 * r];
        if (v[r] < mn) mn = v[r];
    }
#pragma unroll
    for (int off = 16; off; off >>= 1) {
        unsigned long long o = __shfl_xor_sync(0xFFFFFFFFu, mn, off);
        if (o < mn) mn = o;
    }
    const float thr = unfkey((unsigned int)(mn >> 32)) + MARGIN;

    const int b = tok >> 10, hw = tok & 1023;
    const float* xt = x + (size_t)b * C_ * HW_ + hw;
    float xr[8];
#pragma unroll
    for (int q = 0; q < 8; q++)
        xr[q] = xt[(size_t)(lane + 32 * q) * HW_];

    float best_s = __uint_as_float(0x7F800000u);   // +inf
    unsigned int best_j = 0xFFFFFFFFu;
#pragma unroll 1
    for (int r = 0; r < 8; r++) {
        float sf = unfkey((unsigned int)(v[r] >> 32));
        unsigned int m = __ballot_sync(0xFFFFFFFFu, sf <= thr);
        while (m) {
            int src = __ffs(m) - 1;
            m &= m - 1;
            unsigned long long c = __shfl_sync(0xFFFFFFFFu, v[r], src);
            unsigned int j = (unsigned int)c;
            const float* row = cb + (size_t)j * C_;
            float dot = 0.0f;
#pragma unroll
            for (int q = 0; q < 8; q++)
                dot = fmaf(xr[q], row[lane + 32 * q], dot);
#pragma unroll
            for (int off = 16; off; off >>= 1)
                dot += __shfl_xor_sync(0xFFFFFFFFu, dot, off);
            float sc = fmaf(-2.0f, dot, g_cnorm[j]);
            if (sc < best_s || (sc == best_s && j < best_j)) {
                best_s = sc;
                best_j = j;
            }
        }
    }
    if (lane == 0) g_idx[tok] = best_j;
}

// ---------------------------------------------------------------------------
// Kernel 4: gather q, write qe + indices, per-block loss partials
__global__ void gather_kernel(const float* __restrict__ x,
                              const float* __restrict__ cb,
                              float* __restrict__ out) {
    const int bc = blockIdx.x;
    const int b = bc >> 8, c = bc & 255;
    const float* xrow = x + (size_t)bc * HW_;
    float* orow = out + (size_t)bc * HW_;
    float lsum = 0.0f;
#pragma unroll
    for (int r = 0; r < 4; r++) {
        int hw = threadIdx.x + r * 256;
        int n = b * HW_ + hw;
        unsigned int idx = g_idx[n];
        float q = cb[(size_t)idx * C_ + c];
        float dd = xrow[hw] - q;
        lsum += dd * dd;
        orow[hw] = q;
        if (c == 0) out[NQE + 1 + n] = (float)idx;
    }
    __shared__ float red[256];
    red[threadIdx.x] = lsum;
    __syncthreads();
#pragma unroll
    for (int s = 128; s; s >>= 1) {
        if (threadIdx.x < s) red[threadIdx.x] += red[threadIdx.x + s];
        __syncthreads();
    }
    if (threadIdx.x == 0) g_partial[bc] = red[0];
}

// Kernel 5: deterministic final loss reduction
__global__ void loss_kernel(float* __restrict__ out) {
    __shared__ float red[256];
    float s = 0.0f;
    for (int i = threadIdx.x; i < B_ * C_; i += 256) s += g_partial[i];
    red[threadIdx.x] = s;
    __syncthreads();
#pragma unroll
    for (int st = 128; st; st >>= 1) {
        if (threadIdx.x < st) red[threadIdx.x] += red[threadIdx.x + st];
        __syncthreads();
    }
    if (threadIdx.x == 0)
        out[NQE] = red[0] / (float)((size_t)N_ * C_);
}

// ---------------------------------------------------------------------------
extern "C" void kernel_launch(void* const* d_in, const int* in_sizes, int n_in,
                              void* d_out, int out_size) {
    const float* x  = (const float*)d_in[0];   // [16,256,32,32]
    const float* cb = (const float*)d_in[1];   // [8192,256]
    float* out = (float*)d_out;                // [qe | loss | indices]

    cudaFuncSetAttribute(argmin_mma_kernel,
                         cudaFuncAttributeMaxDynamicSharedMemorySize,
                         SMEM_BYTES);

    cnorm_kernel<<<K_ / 8, 256>>>(cb);
    dim3 grid(N_ / TM, K_ / TN);
    argmin_mma_kernel<<<grid, 256, SMEM_BYTES>>>(x, cb);
    rerank_kernel<<<N_ / 8, 256>>>(x, cb);
    gather_kernel<<<B_ * C_, 256>>>(x, cb, out);
    loss_kernel<<<1, 256>>>(out);
}